// round 15
// baseline (speedup 1.0000x reference)
#include <cuda_runtime.h>
#include <cuda_bf16.h>

// y[m] = 0.75 * sum_k( x[m,k] * wcs[k] ),  wcs[k] = sum_n weight[n,k]
// x: [M,K] fp32, weight: [N,K] fp32, out: [M,1] fp32.  M=K=N=8192.
// HBM-streaming: 512 MiB compulsory traffic; plateau so far 6.4 TB/s.
//
// R15 change: 32B per thread (2 consecutive float4) in BOTH kernels ->
// 1024B contiguous per warp-instruction (longer HBM bursts), 2x per-thread MLP.
//
//  0) cudaMemsetAsync zeroes g_wcs (graph memset node)
//  1) colsum: grid (4 x 74) = 296 blocks x 256 thr; each thread sums ~110 rows
//     of TWO consecutive float4 columns; 8 atomicAdds (74-way fan-in, proven).
//  2) rowdot: 8192 blocks x 256 thr, one row per block, 4 iters x 2 float4.

#define MM 8192
#define KK 8192
#define NN 8192
#define COL4 (KK / 4)   // 2048 float4 per row

__device__ float g_wcs[KK];

// ------------------------------------------------- column sum of weight[N,K]
#define CS_THREADS 256
#define CHUNKS 74        // atomic fan-in per address = 74

__global__ __launch_bounds__(CS_THREADS) void colsum_kernel(const float* __restrict__ weight) {
    const int grp  = blockIdx.x * CS_THREADS + threadIdx.x;     // 0..1023
    const int col4 = grp * 2;                                   // two consecutive float4
    const int r0 = (int)(((long long)blockIdx.y * NN) / CHUNKS);
    const int r1 = (int)(((long long)(blockIdx.y + 1) * NN) / CHUNKS);

    const float4* __restrict__ w4 = reinterpret_cast<const float4*>(weight) + col4;

    float4 a0 = make_float4(0.f, 0.f, 0.f, 0.f);
    float4 a1 = make_float4(0.f, 0.f, 0.f, 0.f);
#pragma unroll 4
    for (int r = r0; r < r1; ++r) {
        const float4* p = w4 + (size_t)r * COL4;
        float4 v0 = __ldcs(p);
        float4 v1 = __ldcs(p + 1);
        a0.x += v0.x; a0.y += v0.y; a0.z += v0.z; a0.w += v0.w;
        a1.x += v1.x; a1.y += v1.y; a1.z += v1.z; a1.w += v1.w;
    }

    const int col = col4 * 4;
    atomicAdd(&g_wcs[col + 0], a0.x);
    atomicAdd(&g_wcs[col + 1], a0.y);
    atomicAdd(&g_wcs[col + 2], a0.z);
    atomicAdd(&g_wcs[col + 3], a0.w);
    atomicAdd(&g_wcs[col + 4], a1.x);
    atomicAdd(&g_wcs[col + 5], a1.y);
    atomicAdd(&g_wcs[col + 6], a1.z);
    atomicAdd(&g_wcs[col + 7], a1.w);
}

// ------------------------------------------------- per-row dot with g_wcs
#define DOT_THREADS 256

__global__ __launch_bounds__(DOT_THREADS) void rowdot_kernel(const float* __restrict__ x,
                                                             float* __restrict__ out) {
    const int row = blockIdx.x;
    const float4* __restrict__ x4 = reinterpret_cast<const float4*>(x) + (size_t)row * COL4;
    const float4* __restrict__ w4 = reinterpret_cast<const float4*>(g_wcs);

    float acc = 0.0f;
#pragma unroll
    for (int i = 0; i < COL4 / (DOT_THREADS * 2); ++i) {   // 4 iterations
        const int idx = i * DOT_THREADS * 2 + threadIdx.x * 2;  // 2 consecutive float4
        float4 xv0 = __ldcs(x4 + idx);
        float4 xv1 = __ldcs(x4 + idx + 1);
        float4 wv0 = w4[idx];
        float4 wv1 = w4[idx + 1];
        acc = fmaf(xv0.x, wv0.x, acc);
        acc = fmaf(xv0.y, wv0.y, acc);
        acc = fmaf(xv0.z, wv0.z, acc);
        acc = fmaf(xv0.w, wv0.w, acc);
        acc = fmaf(xv1.x, wv1.x, acc);
        acc = fmaf(xv1.y, wv1.y, acc);
        acc = fmaf(xv1.z, wv1.z, acc);
        acc = fmaf(xv1.w, wv1.w, acc);
    }

    // warp reduce
#pragma unroll
    for (int off = 16; off > 0; off >>= 1)
        acc += __shfl_down_sync(0xFFFFFFFFu, acc, off);

    __shared__ float warp_sums[DOT_THREADS / 32];
    const int lane = threadIdx.x & 31;
    const int wid  = threadIdx.x >> 5;
    if (lane == 0) warp_sums[wid] = acc;
    __syncthreads();

    if (wid == 0) {
        float s = (lane < DOT_THREADS / 32) ? warp_sums[lane] : 0.0f;
#pragma unroll
        for (int off = 4; off > 0; off >>= 1)
            s += __shfl_down_sync(0xFFFFFFFFu, s, off);
        if (lane == 0) out[row] = 0.75f * s;
    }
}

// ---------------------------------------------------------------- launcher
extern "C" void kernel_launch(void* const* d_in, const int* in_sizes, int n_in,
                              void* d_out, int out_size) {
    const float* x      = (const float*)d_in[0];
    const float* weight = (const float*)d_in[1];
    float* out = (float*)d_out;

    void* wcs_ptr = nullptr;
    cudaGetSymbolAddress(&wcs_ptr, g_wcs);
    cudaMemsetAsync(wcs_ptr, 0, KK * sizeof(float));   // graph memset node

    dim3 cs_grid(COL4 / (CS_THREADS * 2), CHUNKS);     // (4, 74) = 296 blocks
    colsum_kernel<<<cs_grid, CS_THREADS>>>(weight);

    rowdot_kernel<<<MM, DOT_THREADS>>>(x, out);
}

// round 16
// speedup vs baseline: 1.0540x; 1.0540x over previous
#include <cuda_runtime.h>
#include <cuda_bf16.h>

// y[m] = 0.75 * sum_k( x[m,k] * wcs[k] ),  wcs[k] = sum_n weight[n,k]
// x: [M,K] fp32, weight: [N,K] fp32, out: [M,1] fp32.  M=K=N=8192.
// HBM-streaming: 512 MiB compulsory traffic; measured platform ceiling for
// this pattern ~6.4 TB/s -> ~80.5us floor. Champion config (R9) + 512-thr rowdot.
//
//  0) cudaMemsetAsync zeroes g_wcs (graph memset node, ~1us)
//  1) colsum: float2/thread, grid (16 x 74) = 1184 blocks x 256 thr
//     (100% occ, 74-way atomic fan-in — proven cheap)
//  2) rowdot: 8192 blocks x 512 thr, one row per block, 4 float4 iters
//     (halved per-block epilogue count vs 256-thr version)

#define MM 8192
#define KK 8192
#define NN 8192
#define COL4 (KK / 4)   // 2048 float4 per row
#define COL2 (KK / 2)   // 4096 float2 per row

__device__ float g_wcs[KK];

// ------------------------------------------------- column sum of weight[N,K]
#define CS_THREADS 256
#define CHUNKS 74        // atomic fan-in per address = 74

__global__ __launch_bounds__(CS_THREADS) void colsum_kernel(const float* __restrict__ weight) {
    const int col2 = blockIdx.x * CS_THREADS + threadIdx.x;       // 0..4095
    const int r0 = (int)(((long long)blockIdx.y * NN) / CHUNKS);  // ~110 rows/chunk
    const int r1 = (int)(((long long)(blockIdx.y + 1) * NN) / CHUNKS);

    const float2* __restrict__ w2 = reinterpret_cast<const float2*>(weight) + col2;

    float2 acc = make_float2(0.f, 0.f);
#pragma unroll 8
    for (int r = r0; r < r1; ++r) {
        float2 v = __ldcs(w2 + (size_t)r * COL2);
        acc.x += v.x; acc.y += v.y;
    }

    const int col = col2 * 2;
    atomicAdd(&g_wcs[col + 0], acc.x);
    atomicAdd(&g_wcs[col + 1], acc.y);
}

// ------------------------------------------------- per-row dot with g_wcs
#define DOT_THREADS 512

__global__ __launch_bounds__(DOT_THREADS) void rowdot_kernel(const float* __restrict__ x,
                                                             float* __restrict__ out) {
    const int row = blockIdx.x;
    const float4* __restrict__ x4 = reinterpret_cast<const float4*>(x) + (size_t)row * COL4;
    const float4* __restrict__ w4 = reinterpret_cast<const float4*>(g_wcs);

    float acc = 0.0f;
#pragma unroll
    for (int i = 0; i < COL4 / DOT_THREADS; ++i) {   // 4 iterations
        const int idx = i * DOT_THREADS + threadIdx.x;
        float4 xv = x4[idx];
        float4 wv = w4[idx];
        acc = fmaf(xv.x, wv.x, acc);
        acc = fmaf(xv.y, wv.y, acc);
        acc = fmaf(xv.z, wv.z, acc);
        acc = fmaf(xv.w, wv.w, acc);
    }

    // warp reduce
#pragma unroll
    for (int off = 16; off > 0; off >>= 1)
        acc += __shfl_down_sync(0xFFFFFFFFu, acc, off);

    __shared__ float warp_sums[DOT_THREADS / 32];
    const int lane = threadIdx.x & 31;
    const int wid  = threadIdx.x >> 5;
    if (lane == 0) warp_sums[wid] = acc;
    __syncthreads();

    if (wid == 0) {
        float s = (lane < DOT_THREADS / 32) ? warp_sums[lane] : 0.0f;
#pragma unroll
        for (int off = 8; off > 0; off >>= 1)
            s += __shfl_down_sync(0xFFFFFFFFu, s, off);
        if (lane == 0) out[row] = 0.75f * s;
    }
}

// ---------------------------------------------------------------- launcher
extern "C" void kernel_launch(void* const* d_in, const int* in_sizes, int n_in,
                              void* d_out, int out_size) {
    const float* x      = (const float*)d_in[0];
    const float* weight = (const float*)d_in[1];
    float* out = (float*)d_out;

    void* wcs_ptr = nullptr;
    cudaGetSymbolAddress(&wcs_ptr, g_wcs);
    cudaMemsetAsync(wcs_ptr, 0, KK * sizeof(float));   // graph memset node

    dim3 cs_grid(COL2 / CS_THREADS, CHUNKS);           // (16, 74) = 1184 blocks
    colsum_kernel<<<cs_grid, CS_THREADS>>>(weight);

    rowdot_kernel<<<MM, DOT_THREADS>>>(x, out);
}